// round 12
// baseline (speedup 1.0000x reference)
#include <cuda_runtime.h>
#include <cuda_fp16.h>

// out[v] = sum over edges (u->v) of emb[u], D_FEAT = 64 fp32.
// R11 (resubmit after infra failure): same fp16 hot path as R10, but the
// 25.6MB replica-accumulator zeroing moves from a store-issue-bound kernel
// to a graph memset node.
//  m1: cudaMemsetAsync(g_acc, 0)          (driver memset, full BW)
//  k1: convert emb fp32 -> fp16 table
//  k2: edge-parallel push, red.global.add.noftz.v4.f16x2 into replica (e&3)
//  k3: combine 4 fp16 replicas -> fp32 out (covers every element, no d_out memset)

#define N_NODES_MAX 50000
#define D_FEAT 64
#define N_REP 4

__device__ __half g_embh[N_NODES_MAX * D_FEAT];
__device__ __half g_acc[N_REP][N_NODES_MAX * D_FEAT];

// Convert 8 floats -> 8 halves per thread (two float4 loads, one uint4 store).
__global__ void convert_kernel(const float4* __restrict__ emb, int n_conv) {
    int i = blockIdx.x * blockDim.x + threadIdx.x;
    if (i >= n_conv) return;
    float4 a = __ldg(&emb[i * 2 + 0]);
    float4 b = __ldg(&emb[i * 2 + 1]);
    __half2 h0 = __floats2half2_rn(a.x, a.y);
    __half2 h1 = __floats2half2_rn(a.z, a.w);
    __half2 h2 = __floats2half2_rn(b.x, b.y);
    __half2 h3 = __floats2half2_rn(b.z, b.w);
    uint4 packed;
    packed.x = *reinterpret_cast<unsigned int*>(&h0);
    packed.y = *reinterpret_cast<unsigned int*>(&h1);
    packed.z = *reinterpret_cast<unsigned int*>(&h2);
    packed.w = *reinterpret_cast<unsigned int*>(&h3);
    reinterpret_cast<uint4*>(g_embh)[i] = packed;
}

__device__ __forceinline__ void red_add_v4h2(__half* p, uint4 v) {
    asm volatile("red.global.add.noftz.v4.f16x2 [%0], {%1, %2, %3, %4};"
                 :: "l"(p), "r"(v.x), "r"(v.y), "r"(v.z), "r"(v.w) : "memory");
}

__global__ void edge_scatter_h2_kernel(const int* __restrict__ src,
                                       const int* __restrict__ dst,
                                       int n_edges) {
    long long t = (long long)blockIdx.x * blockDim.x + threadIdx.x;
    int q = (int)(t >> 3);     // edge-quad index
    int c = (int)(t & 7);      // 16B (8-half) chunk within the 128B row
    int e0 = q * 4;
    if (e0 >= n_edges) return;

    const uint4* tbl = reinterpret_cast<const uint4*>(g_embh);

    if (e0 + 3 < n_edges) {
        int4 s = __ldg((const int4*)(src + e0));
        int4 d = __ldg((const int4*)(dst + e0));

        // 4 independent gather chains (16B each), overlap L2 latency.
        uint4 v0 = __ldg(tbl + (long long)s.x * 8 + c);
        uint4 v1 = __ldg(tbl + (long long)s.y * 8 + c);
        uint4 v2 = __ldg(tbl + (long long)s.z * 8 + c);
        uint4 v3 = __ldg(tbl + (long long)s.w * 8 + c);

        // edge e0+i -> replica i
        red_add_v4h2(g_acc[0] + ((long long)d.x * D_FEAT + c * 8), v0);
        red_add_v4h2(g_acc[1] + ((long long)d.y * D_FEAT + c * 8), v1);
        red_add_v4h2(g_acc[2] + ((long long)d.z * D_FEAT + c * 8), v2);
        red_add_v4h2(g_acc[3] + ((long long)d.w * D_FEAT + c * 8), v3);
    } else {
        for (int e = e0; e < n_edges; e++) {
            int s = src[e];
            int d = dst[e];
            uint4 v = __ldg(tbl + (long long)s * 8 + c);
            red_add_v4h2(g_acc[e & 3] + ((long long)d * D_FEAT + c * 8), v);
        }
    }
}

// out fp32 = sum of 4 fp16 replicas.  Thread handles 8 floats.
__global__ void combine_kernel(float4* __restrict__ out, int n_grp8) {
    int i = blockIdx.x * blockDim.x + threadIdx.x;
    if (i >= n_grp8) return;

    float acc[8];
#pragma unroll
    for (int k = 0; k < 8; k++) acc[k] = 0.f;

#pragma unroll
    for (int r = 0; r < N_REP; r++) {
        uint4 v = __ldg(reinterpret_cast<const uint4*>(g_acc[r]) + i);
        const unsigned int w[4] = {v.x, v.y, v.z, v.w};
#pragma unroll
        for (int k = 0; k < 4; k++) {
            __half2 h = *reinterpret_cast<const __half2*>(&w[k]);
            float2 f = __half22float2(h);
            acc[2 * k + 0] += f.x;
            acc[2 * k + 1] += f.y;
        }
    }

    out[i * 2 + 0] = make_float4(acc[0], acc[1], acc[2], acc[3]);
    out[i * 2 + 1] = make_float4(acc[4], acc[5], acc[6], acc[7]);
}

extern "C" void kernel_launch(void* const* d_in, const int* in_sizes, int n_in,
                              void* d_out, int out_size) {
    const float4* emb = (const float4*)d_in[0];
    const int*    src = (const int*)d_in[1];
    const int*    dst = (const int*)d_in[2];

    int n_elems = in_sizes[0];            // n_nodes * 64 floats
    int n_edges = in_sizes[1];
    int n_nodes = out_size / D_FEAT;

    // Zero the replica accumulators with a graph memset node (full-BW path).
    void* acc_ptr = nullptr;
    cudaGetSymbolAddress(&acc_ptr, g_acc);  // address query only; capture-safe
    cudaMemsetAsync(acc_ptr, 0,
                    (size_t)N_REP * n_nodes * D_FEAT * sizeof(__half));

    int n_conv = n_elems / 8;
    convert_kernel<<<(n_conv + 255) / 256, 256>>>(emb, n_conv);

    int n_quads = (n_edges + 3) / 4;
    long long total_threads = (long long)n_quads * 8;
    int grid = (int)((total_threads + 255) / 256);
    edge_scatter_h2_kernel<<<grid, 256>>>(src, dst, n_edges);

    int n_grp8 = out_size / 8;
    combine_kernel<<<(n_grp8 + 255) / 256, 256>>>((float4*)d_out, n_grp8);
}

// round 13
// speedup vs baseline: 1.3966x; 1.3966x over previous
#include <cuda_runtime.h>
#include <cuda_fp16.h>

// out[v] = sum over edges (u->v) of emb[u], D_FEAT = 64 fp32.
// R13: no zeroing pass at all.
//  - __device__ g_acc is zero-initialized at module load.
//  - combine_kernel writes zeros back to g_acc after reading it, so every
//    invocation (correctness run, each graph replay) restores the invariant.
//  k1: convert emb fp32 -> fp16 table (MLP=4: 4 independent float4 loads)
//  k2: edge-parallel push, red.global.add.noftz.v4.f16x2 into replica (e&3)
//  k3: combine 4 fp16 replicas -> fp32 out, then re-zero the replicas.

#define N_NODES_MAX 50000
#define D_FEAT 64
#define N_REP 4

__device__ __half g_embh[N_NODES_MAX * D_FEAT];
__device__ __half g_acc[N_REP][N_NODES_MAX * D_FEAT];  // zero-init at load

// Each thread converts 16 floats: 4 independent float4 loads, 2 uint4 stores.
__global__ void convert_kernel(const float4* __restrict__ emb, int n_grp16) {
    int i = blockIdx.x * blockDim.x + threadIdx.x;
    if (i >= n_grp16) return;
    float4 a = __ldg(&emb[i * 4 + 0]);
    float4 b = __ldg(&emb[i * 4 + 1]);
    float4 cc = __ldg(&emb[i * 4 + 2]);
    float4 d = __ldg(&emb[i * 4 + 3]);

    __half2 h0 = __floats2half2_rn(a.x, a.y);
    __half2 h1 = __floats2half2_rn(a.z, a.w);
    __half2 h2 = __floats2half2_rn(b.x, b.y);
    __half2 h3 = __floats2half2_rn(b.z, b.w);
    __half2 h4 = __floats2half2_rn(cc.x, cc.y);
    __half2 h5 = __floats2half2_rn(cc.z, cc.w);
    __half2 h6 = __floats2half2_rn(d.x, d.y);
    __half2 h7 = __floats2half2_rn(d.z, d.w);

    uint4 p0, p1;
    p0.x = *reinterpret_cast<unsigned int*>(&h0);
    p0.y = *reinterpret_cast<unsigned int*>(&h1);
    p0.z = *reinterpret_cast<unsigned int*>(&h2);
    p0.w = *reinterpret_cast<unsigned int*>(&h3);
    p1.x = *reinterpret_cast<unsigned int*>(&h4);
    p1.y = *reinterpret_cast<unsigned int*>(&h5);
    p1.z = *reinterpret_cast<unsigned int*>(&h6);
    p1.w = *reinterpret_cast<unsigned int*>(&h7);
    reinterpret_cast<uint4*>(g_embh)[i * 2 + 0] = p0;
    reinterpret_cast<uint4*>(g_embh)[i * 2 + 1] = p1;
}

__device__ __forceinline__ void red_add_v4h2(__half* p, uint4 v) {
    asm volatile("red.global.add.noftz.v4.f16x2 [%0], {%1, %2, %3, %4};"
                 :: "l"(p), "r"(v.x), "r"(v.y), "r"(v.z), "r"(v.w) : "memory");
}

__global__ void edge_scatter_h2_kernel(const int* __restrict__ src,
                                       const int* __restrict__ dst,
                                       int n_edges) {
    long long t = (long long)blockIdx.x * blockDim.x + threadIdx.x;
    int q = (int)(t >> 3);     // edge-quad index
    int c = (int)(t & 7);      // 16B (8-half) chunk within the 128B row
    int e0 = q * 4;
    if (e0 >= n_edges) return;

    const uint4* tbl = reinterpret_cast<const uint4*>(g_embh);

    if (e0 + 3 < n_edges) {
        int4 s = __ldg((const int4*)(src + e0));
        int4 d = __ldg((const int4*)(dst + e0));

        // 4 independent gather chains (16B each), overlap L2 latency.
        uint4 v0 = __ldg(tbl + (long long)s.x * 8 + c);
        uint4 v1 = __ldg(tbl + (long long)s.y * 8 + c);
        uint4 v2 = __ldg(tbl + (long long)s.z * 8 + c);
        uint4 v3 = __ldg(tbl + (long long)s.w * 8 + c);

        // edge e0+i -> replica i
        red_add_v4h2(g_acc[0] + ((long long)d.x * D_FEAT + c * 8), v0);
        red_add_v4h2(g_acc[1] + ((long long)d.y * D_FEAT + c * 8), v1);
        red_add_v4h2(g_acc[2] + ((long long)d.z * D_FEAT + c * 8), v2);
        red_add_v4h2(g_acc[3] + ((long long)d.w * D_FEAT + c * 8), v3);
    } else {
        for (int e = e0; e < n_edges; e++) {
            int s = src[e];
            int d = dst[e];
            uint4 v = __ldg(tbl + (long long)s * 8 + c);
            red_add_v4h2(g_acc[e & 3] + ((long long)d * D_FEAT + c * 8), v);
        }
    }
}

// out fp32 = sum of 4 fp16 replicas; then re-zero the replicas so the next
// invocation starts from a clean accumulator (no separate zeroing pass).
__global__ void combine_kernel(float4* __restrict__ out, int n_grp8) {
    int i = blockIdx.x * blockDim.x + threadIdx.x;
    if (i >= n_grp8) return;

    float acc[8];
#pragma unroll
    for (int k = 0; k < 8; k++) acc[k] = 0.f;

    const uint4 zero4 = make_uint4(0u, 0u, 0u, 0u);
#pragma unroll
    for (int r = 0; r < N_REP; r++) {
        uint4 v = __ldg(reinterpret_cast<const uint4*>(g_acc[r]) + i);
        const unsigned int w[4] = {v.x, v.y, v.z, v.w};
#pragma unroll
        for (int k = 0; k < 4; k++) {
            __half2 h = *reinterpret_cast<const __half2*>(&w[k]);
            float2 f = __half22float2(h);
            acc[2 * k + 0] += f.x;
            acc[2 * k + 1] += f.y;
        }
        reinterpret_cast<uint4*>(g_acc[r])[i] = zero4;  // restore invariant
    }

    out[i * 2 + 0] = make_float4(acc[0], acc[1], acc[2], acc[3]);
    out[i * 2 + 1] = make_float4(acc[4], acc[5], acc[6], acc[7]);
}

extern "C" void kernel_launch(void* const* d_in, const int* in_sizes, int n_in,
                              void* d_out, int out_size) {
    const float4* emb = (const float4*)d_in[0];
    const int*    src = (const int*)d_in[1];
    const int*    dst = (const int*)d_in[2];

    int n_elems = in_sizes[0];            // n_nodes * 64 floats
    int n_edges = in_sizes[1];

    int n_grp16 = n_elems / 16;           // D_FEAT=64 divisible by 16
    convert_kernel<<<(n_grp16 + 255) / 256, 256>>>(emb, n_grp16);

    int n_quads = (n_edges + 3) / 4;
    long long total_threads = (long long)n_quads * 8;
    int grid = (int)((total_threads + 255) / 256);
    edge_scatter_h2_kernel<<<grid, 256>>>(src, dst, n_edges);

    int n_grp8 = out_size / 8;
    combine_kernel<<<(n_grp8 + 255) / 256, 256>>>((float4*)d_out, n_grp8);
}

// round 14
// speedup vs baseline: 1.5011x; 1.0748x over previous
#include <cuda_runtime.h>
#include <cuda_fp16.h>

// out[v] = sum over edges (u->v) of emb[u], D_FEAT = 64 fp32.
// R14 = R10 structure with the prep phase split into two INDEPENDENT kernels
// run concurrently via captured fork-join:
//   zero_kernel   (25.6MB stores, no deps)   ── on side stream
//   convert_kernel(emb fp32 -> fp16 table)   ── on main stream
// then: edge-parallel fp16 push scatter (replica e&3), then fp32 combine.

#define N_NODES_MAX 50000
#define D_FEAT 64
#define N_REP 4

__device__ __half g_embh[N_NODES_MAX * D_FEAT];
__device__ __half g_acc[N_REP][N_NODES_MAX * D_FEAT];

__global__ void zero_kernel(int n_zero16) {
    int i = blockIdx.x * blockDim.x + threadIdx.x;
    if (i < n_zero16)
        reinterpret_cast<uint4*>(g_acc)[i] = make_uint4(0u, 0u, 0u, 0u);
}

// Convert 8 floats -> 8 halves per thread (two float4 loads, one uint4 store).
__global__ void convert_kernel(const float4* __restrict__ emb, int n_conv) {
    int i = blockIdx.x * blockDim.x + threadIdx.x;
    if (i >= n_conv) return;
    float4 a = __ldg(&emb[i * 2 + 0]);
    float4 b = __ldg(&emb[i * 2 + 1]);
    __half2 h0 = __floats2half2_rn(a.x, a.y);
    __half2 h1 = __floats2half2_rn(a.z, a.w);
    __half2 h2 = __floats2half2_rn(b.x, b.y);
    __half2 h3 = __floats2half2_rn(b.z, b.w);
    uint4 packed;
    packed.x = *reinterpret_cast<unsigned int*>(&h0);
    packed.y = *reinterpret_cast<unsigned int*>(&h1);
    packed.z = *reinterpret_cast<unsigned int*>(&h2);
    packed.w = *reinterpret_cast<unsigned int*>(&h3);
    reinterpret_cast<uint4*>(g_embh)[i] = packed;
}

__device__ __forceinline__ void red_add_v4h2(__half* p, uint4 v) {
    asm volatile("red.global.add.noftz.v4.f16x2 [%0], {%1, %2, %3, %4};"
                 :: "l"(p), "r"(v.x), "r"(v.y), "r"(v.z), "r"(v.w) : "memory");
}

__global__ void edge_scatter_h2_kernel(const int* __restrict__ src,
                                       const int* __restrict__ dst,
                                       int n_edges) {
    long long t = (long long)blockIdx.x * blockDim.x + threadIdx.x;
    int q = (int)(t >> 3);     // edge-quad index
    int c = (int)(t & 7);      // 16B (8-half) chunk within the 128B row
    int e0 = q * 4;
    if (e0 >= n_edges) return;

    const uint4* tbl = reinterpret_cast<const uint4*>(g_embh);

    if (e0 + 3 < n_edges) {
        int4 s = __ldg((const int4*)(src + e0));
        int4 d = __ldg((const int4*)(dst + e0));

        uint4 v0 = __ldg(tbl + (long long)s.x * 8 + c);
        uint4 v1 = __ldg(tbl + (long long)s.y * 8 + c);
        uint4 v2 = __ldg(tbl + (long long)s.z * 8 + c);
        uint4 v3 = __ldg(tbl + (long long)s.w * 8 + c);

        red_add_v4h2(g_acc[0] + ((long long)d.x * D_FEAT + c * 8), v0);
        red_add_v4h2(g_acc[1] + ((long long)d.y * D_FEAT + c * 8), v1);
        red_add_v4h2(g_acc[2] + ((long long)d.z * D_FEAT + c * 8), v2);
        red_add_v4h2(g_acc[3] + ((long long)d.w * D_FEAT + c * 8), v3);
    } else {
        for (int e = e0; e < n_edges; e++) {
            int s = src[e];
            int d = dst[e];
            uint4 v = __ldg(tbl + (long long)s * 8 + c);
            red_add_v4h2(g_acc[e & 3] + ((long long)d * D_FEAT + c * 8), v);
        }
    }
}

// out fp32 = sum of 4 fp16 replicas.  Thread handles 8 floats.
__global__ void combine_kernel(float4* __restrict__ out, int n_grp8) {
    int i = blockIdx.x * blockDim.x + threadIdx.x;
    if (i >= n_grp8) return;

    float acc[8];
#pragma unroll
    for (int k = 0; k < 8; k++) acc[k] = 0.f;

#pragma unroll
    for (int r = 0; r < N_REP; r++) {
        uint4 v = __ldg(reinterpret_cast<const uint4*>(g_acc[r]) + i);
        const unsigned int w[4] = {v.x, v.y, v.z, v.w};
#pragma unroll
        for (int k = 0; k < 4; k++) {
            __half2 h = *reinterpret_cast<const __half2*>(&w[k]);
            float2 f = __half22float2(h);
            acc[2 * k + 0] += f.x;
            acc[2 * k + 1] += f.y;
        }
    }

    out[i * 2 + 0] = make_float4(acc[0], acc[1], acc[2], acc[3]);
    out[i * 2 + 1] = make_float4(acc[4], acc[5], acc[6], acc[7]);
}

// Side stream + events, created once on the first (non-capturing) call.
struct SideStream {
    cudaStream_t s;
    cudaEvent_t fork, join;
    SideStream() {
        cudaStreamCreateWithFlags(&s, cudaStreamNonBlocking);
        cudaEventCreateWithFlags(&fork, cudaEventDisableTiming);
        cudaEventCreateWithFlags(&join, cudaEventDisableTiming);
    }
};

extern "C" void kernel_launch(void* const* d_in, const int* in_sizes, int n_in,
                              void* d_out, int out_size) {
    static SideStream ss;  // constructed on correctness run (no capture active)

    const float4* emb = (const float4*)d_in[0];
    const int*    src = (const int*)d_in[1];
    const int*    dst = (const int*)d_in[2];

    int n_elems = in_sizes[0];            // n_nodes * 64 floats
    int n_edges = in_sizes[1];
    int n_nodes = out_size / D_FEAT;

    // Fork: side stream zeroes the replica accumulators while the main
    // stream converts emb to fp16.
    cudaEventRecord(ss.fork, 0);
    cudaStreamWaitEvent(ss.s, ss.fork, 0);

    int n_zero16 = (n_nodes * D_FEAT * N_REP) / 8;
    zero_kernel<<<(n_zero16 + 255) / 256, 256, 0, ss.s>>>(n_zero16);
    cudaEventRecord(ss.join, ss.s);

    int n_conv = n_elems / 8;
    convert_kernel<<<(n_conv + 255) / 256, 256>>>(emb, n_conv);

    // Join before the scatter (needs both embh and zeroed g_acc).
    cudaStreamWaitEvent(0, ss.join, 0);

    int n_quads = (n_edges + 3) / 4;
    long long total_threads = (long long)n_quads * 8;
    int grid = (int)((total_threads + 255) / 256);
    edge_scatter_h2_kernel<<<grid, 256>>>(src, dst, n_edges);

    int n_grp8 = out_size / 8;
    combine_kernel<<<(n_grp8 + 255) / 256, 256>>>((float4*)d_out, n_grp8);
}

// round 15
// speedup vs baseline: 1.5651x; 1.0427x over previous
#include <cuda_runtime.h>
#include <cuda_fp16.h>

// out[v] = sum over edges (u->v) of emb[u], D_FEAT = 64 fp32.
// R15 = R10 single-stream structure, N_REP=2, MLP=4 prep.
//  k1: fused prep — thread i zeroes 4 uint4 of g_acc (12.8MB total) and
//      converts 16 floats of emb -> fp16 table (4 independent float4 loads).
//  k2: edge-parallel push, red.global.add.noftz.v4.f16x2 into replica (e&1).
//  k3: combine 2 fp16 replicas -> fp32 out.

#define N_NODES_MAX 50000
#define D_FEAT 64
#define N_REP 2

__device__ __half g_embh[N_NODES_MAX * D_FEAT];
__device__ __half g_acc[N_REP][N_NODES_MAX * D_FEAT];

// i < n_zero4  : zero uint4s [i*4, i*4+4) of g_acc  (n_zero4 = zero16/4)
// i < n_grp16  : convert emb floats [i*16, i*16+16) -> g_embh
__global__ void prep_kernel(const float4* __restrict__ emb,
                            int n_grp16, int n_zero4) {
    int i = blockIdx.x * blockDim.x + threadIdx.x;

    if (i < n_zero4) {
        uint4 z = make_uint4(0u, 0u, 0u, 0u);
        uint4* p = reinterpret_cast<uint4*>(g_acc) + i * 4;
        p[0] = z; p[1] = z; p[2] = z; p[3] = z;
    }

    if (i < n_grp16) {
        float4 a = __ldg(&emb[i * 4 + 0]);
        float4 b = __ldg(&emb[i * 4 + 1]);
        float4 c = __ldg(&emb[i * 4 + 2]);
        float4 d = __ldg(&emb[i * 4 + 3]);

        __half2 h0 = __floats2half2_rn(a.x, a.y);
        __half2 h1 = __floats2half2_rn(a.z, a.w);
        __half2 h2 = __floats2half2_rn(b.x, b.y);
        __half2 h3 = __floats2half2_rn(b.z, b.w);
        __half2 h4 = __floats2half2_rn(c.x, c.y);
        __half2 h5 = __floats2half2_rn(c.z, c.w);
        __half2 h6 = __floats2half2_rn(d.x, d.y);
        __half2 h7 = __floats2half2_rn(d.z, d.w);

        uint4 p0, p1;
        p0.x = *reinterpret_cast<unsigned int*>(&h0);
        p0.y = *reinterpret_cast<unsigned int*>(&h1);
        p0.z = *reinterpret_cast<unsigned int*>(&h2);
        p0.w = *reinterpret_cast<unsigned int*>(&h3);
        p1.x = *reinterpret_cast<unsigned int*>(&h4);
        p1.y = *reinterpret_cast<unsigned int*>(&h5);
        p1.z = *reinterpret_cast<unsigned int*>(&h6);
        p1.w = *reinterpret_cast<unsigned int*>(&h7);
        reinterpret_cast<uint4*>(g_embh)[i * 2 + 0] = p0;
        reinterpret_cast<uint4*>(g_embh)[i * 2 + 1] = p1;
    }
}

__device__ __forceinline__ void red_add_v4h2(__half* p, uint4 v) {
    asm volatile("red.global.add.noftz.v4.f16x2 [%0], {%1, %2, %3, %4};"
                 :: "l"(p), "r"(v.x), "r"(v.y), "r"(v.z), "r"(v.w) : "memory");
}

__global__ void edge_scatter_h2_kernel(const int* __restrict__ src,
                                       const int* __restrict__ dst,
                                       int n_edges) {
    long long t = (long long)blockIdx.x * blockDim.x + threadIdx.x;
    int q = (int)(t >> 3);     // edge-quad index
    int c = (int)(t & 7);      // 16B (8-half) chunk within the 128B row
    int e0 = q * 4;
    if (e0 >= n_edges) return;

    const uint4* tbl = reinterpret_cast<const uint4*>(g_embh);

    if (e0 + 3 < n_edges) {
        int4 s = __ldg((const int4*)(src + e0));
        int4 d = __ldg((const int4*)(dst + e0));

        // 4 independent gather chains (16B each), overlap L2 latency.
        uint4 v0 = __ldg(tbl + (long long)s.x * 8 + c);
        uint4 v1 = __ldg(tbl + (long long)s.y * 8 + c);
        uint4 v2 = __ldg(tbl + (long long)s.z * 8 + c);
        uint4 v3 = __ldg(tbl + (long long)s.w * 8 + c);

        // edge e -> replica (e & 1)
        red_add_v4h2(g_acc[0] + ((long long)d.x * D_FEAT + c * 8), v0);
        red_add_v4h2(g_acc[1] + ((long long)d.y * D_FEAT + c * 8), v1);
        red_add_v4h2(g_acc[0] + ((long long)d.z * D_FEAT + c * 8), v2);
        red_add_v4h2(g_acc[1] + ((long long)d.w * D_FEAT + c * 8), v3);
    } else {
        for (int e = e0; e < n_edges; e++) {
            int s = src[e];
            int d = dst[e];
            uint4 v = __ldg(tbl + (long long)s * 8 + c);
            red_add_v4h2(g_acc[e & 1] + ((long long)d * D_FEAT + c * 8), v);
        }
    }
}

// out fp32 = sum of 2 fp16 replicas.  Thread handles 8 floats.
__global__ void combine_kernel(float4* __restrict__ out, int n_grp8) {
    int i = blockIdx.x * blockDim.x + threadIdx.x;
    if (i >= n_grp8) return;

    float acc[8];
#pragma unroll
    for (int k = 0; k < 8; k++) acc[k] = 0.f;

#pragma unroll
    for (int r = 0; r < N_REP; r++) {
        uint4 v = __ldg(reinterpret_cast<const uint4*>(g_acc[r]) + i);
        const unsigned int w[4] = {v.x, v.y, v.z, v.w};
#pragma unroll
        for (int k = 0; k < 4; k++) {
            __half2 h = *reinterpret_cast<const __half2*>(&w[k]);
            float2 f = __half22float2(h);
            acc[2 * k + 0] += f.x;
            acc[2 * k + 1] += f.y;
        }
    }

    out[i * 2 + 0] = make_float4(acc[0], acc[1], acc[2], acc[3]);
    out[i * 2 + 1] = make_float4(acc[4], acc[5], acc[6], acc[7]);
}

extern "C" void kernel_launch(void* const* d_in, const int* in_sizes, int n_in,
                              void* d_out, int out_size) {
    const float4* emb = (const float4*)d_in[0];
    const int*    src = (const int*)d_in[1];
    const int*    dst = (const int*)d_in[2];

    int n_elems = in_sizes[0];            // n_nodes * 64 floats
    int n_edges = in_sizes[1];
    int n_nodes = out_size / D_FEAT;

    int n_grp16 = n_elems / 16;                         // 200K convert threads
    int n_zero16 = (n_nodes * D_FEAT * N_REP) / 8;      // uint4 count
    int n_zero4  = (n_zero16 + 3) / 4;                  // threads zeroing 4 each
    int n_prep = n_grp16 > n_zero4 ? n_grp16 : n_zero4;

    prep_kernel<<<(n_prep + 255) / 256, 256>>>(emb, n_grp16, n_zero4);

    int n_quads = (n_edges + 3) / 4;
    long long total_threads = (long long)n_quads * 8;
    int grid = (int)((total_threads + 255) / 256);
    edge_scatter_h2_kernel<<<grid, 256>>>(src, dst, n_edges);

    int n_grp8 = out_size / 8;
    combine_kernel<<<(n_grp8 + 255) / 256, 256>>>((float4*)d_out, n_grp8);
}